// round 3
// baseline (speedup 1.0000x reference)
#include <cuda_runtime.h>
#include <math.h>

#define BB   256   // batch
#define TT   512   // timesteps
#define DD   64    // input dim
#define HH   512   // hidden
#define G4   2048  // 4*H
#define K0T  576   // D + H   (layer 0 concatenated K)
#define K1T  1024  // H + H   (layer 1 concatenated K)
#define NBLK 128   // persistent grid size (must all be co-resident; 128 <= 148 SMs)

// ---- device scratch (static: no allocation anywhere) ----
__device__ float g_W0[G4 * K0T];     // [2048 x 576]  = [w_ih_0 | w_hh_0]
__device__ float g_W1[G4 * K1T];     // [2048 x 1024] = [w_ih_1 | w_hh_1]
__device__ float g_b0[G4];
__device__ float g_b1[G4];
__device__ float g_h0[2][BB * HH];   // layer-0 h ping-pong (also layer-1 input)
__device__ float g_c0[BB * HH];
__device__ float g_h1[2][BB * HH];
__device__ float g_c1[BB * HH];
__device__ unsigned g_count;         // cumulative grid-barrier counter

// ---------------------------------------------------------------------------
// Pack weights (concat w_ih|w_hh per gate row), pre-add biases, zero states
// and the barrier counter. Runs every kernel_launch call -> deterministic.
// ---------------------------------------------------------------------------
__global__ void pack_kernel(const float* __restrict__ w_ih_0, const float* __restrict__ w_hh_0,
                            const float* __restrict__ b_ih_0, const float* __restrict__ b_hh_0,
                            const float* __restrict__ w_ih_1, const float* __restrict__ w_hh_1,
                            const float* __restrict__ b_ih_1, const float* __restrict__ b_hh_1)
{
    const int stride = gridDim.x * blockDim.x;
    const int idx = blockIdx.x * blockDim.x + threadIdx.x;

    if (idx == 0) g_count = 0u;

    for (int i = idx; i < G4 * K0T; i += stride) {
        int g = i / K0T, k = i % K0T;
        g_W0[i] = (k < DD) ? w_ih_0[g * DD + k] : w_hh_0[g * HH + (k - DD)];
    }
    for (int i = idx; i < G4 * K1T; i += stride) {
        int g = i / K1T, k = i % K1T;
        g_W1[i] = (k < HH) ? w_ih_1[g * HH + k] : w_hh_1[g * HH + (k - HH)];
    }
    for (int i = idx; i < G4; i += stride) {
        g_b0[i] = b_ih_0[i] + b_hh_0[i];
        g_b1[i] = b_ih_1[i] + b_hh_1[i];
    }
    for (int i = idx; i < BB * HH; i += stride) {
        g_h0[0][i] = 0.f; g_c0[i] = 0.f;
        g_h1[0][i] = 0.f; g_c1[i] = 0.f;
    }
}

__device__ __forceinline__ float sigmoidf_(float x) { return 1.0f / (1.0f + expf(-x)); }

// ---------------------------------------------------------------------------
// Grid barrier: cumulative counter, fence-based synchronization.
// Every block must pass every barrier; all NBLK blocks are co-resident.
// ---------------------------------------------------------------------------
__device__ __forceinline__ void grid_barrier(unsigned& target)
{
    __syncthreads();
    if (threadIdx.x == 0) {
        __threadfence();                 // release prior writes
        target += NBLK;
        atomicAdd(&g_count, 1u);
        while (*((volatile unsigned*)&g_count) < target) { }
        __threadfence();                 // acquire others' writes
    }
    __syncthreads();
}

// ---------------------------------------------------------------------------
// One 64(batch) x 64(gatecol) tile of one LSTM timestep, fused epilogue.
// Tile cols = 16 hidden units x 4 gates interleaved as j = 4*ul + gi
//   -> gate row g = gi*512 + u0 + ul. Thread owns 4 batch rows x one unit.
// ---------------------------------------------------------------------------
__device__ __forceinline__ void lstm_tile(
    const float* __restrict__ inA, int ldA, int K1, int KTOT,
    const float* __restrict__ hprev, const float* __restrict__ W,
    const float* __restrict__ bias, float* __restrict__ cst, float* __restrict__ hout,
    int b0, int u0, float (*As)[68], float (*Bs)[68])
{
    const int tid = threadIdx.x;       // 0..255
    const int tx  = tid & 15;          // unit within tile
    const int ty  = tid >> 4;          // batch group

    const int lj  = tid >> 2;          // 0..63 : tile row (A: batch) / tile col (B: gatecol)
    const int lk  = (tid & 3) << 2;    // 0,4,8,12 : k offset within BK=16
    const int gj  = ((lj & 3) << 9) + u0 + (lj >> 2);   // gate row for B load

    float acc[4][4];
    #pragma unroll
    for (int m = 0; m < 4; m++)
        #pragma unroll
        for (int g = 0; g < 4; g++) acc[m][g] = 0.f;

    for (int k0 = 0; k0 < KTOT; k0 += 16) {
        // ---- load A tile (batch x 16k), source switches at K1 (both multiples of 16)
        const float* arow; int ka;
        if (k0 < K1) { arow = inA   + (size_t)(b0 + lj) * ldA; ka = k0 + lk; }
        else         { arow = hprev + (size_t)(b0 + lj) * HH;  ka = k0 - K1 + lk; }
        float4 av = *reinterpret_cast<const float4*>(arow + ka);
        As[lk + 0][lj] = av.x;  As[lk + 1][lj] = av.y;
        As[lk + 2][lj] = av.z;  As[lk + 3][lj] = av.w;

        // ---- load B tile (64 gate rows x 16k)
        float4 bv = *reinterpret_cast<const float4*>(W + (size_t)gj * KTOT + k0 + lk);
        Bs[lk + 0][lj] = bv.x;  Bs[lk + 1][lj] = bv.y;
        Bs[lk + 2][lj] = bv.z;  Bs[lk + 3][lj] = bv.w;

        __syncthreads();

        #pragma unroll
        for (int kk = 0; kk < 16; kk++) {
            float4 a4 = *reinterpret_cast<const float4*>(&As[kk][ty << 2]);
            float4 b4 = *reinterpret_cast<const float4*>(&Bs[kk][tx << 2]);
            float a[4] = {a4.x, a4.y, a4.z, a4.w};
            float b[4] = {b4.x, b4.y, b4.z, b4.w};
            #pragma unroll
            for (int m = 0; m < 4; m++)
                #pragma unroll
                for (int g = 0; g < 4; g++)
                    acc[m][g] += a[m] * b[g];
        }
        __syncthreads();
    }

    // ---- fused LSTM epilogue: this thread = unit (u0+tx), batch rows b0+4*ty..+3
    const int u = u0 + tx;
    const float bi = bias[u];
    const float bf = bias[HH + u];
    const float bg = bias[2 * HH + u];
    const float bo = bias[3 * HH + u];

    #pragma unroll
    for (int m = 0; m < 4; m++) {
        const int b   = b0 + (ty << 2) + m;
        const int idx = b * HH + u;
        float ig = sigmoidf_(acc[m][0] + bi);
        float fg = sigmoidf_(acc[m][1] + bf);
        float gg = tanhf    (acc[m][2] + bg);
        float og = sigmoidf_(acc[m][3] + bo);
        float c  = fg * cst[idx] + ig * gg;
        cst[idx]  = c;
        hout[idx] = og * tanhf(c);
    }
}

// ---------------------------------------------------------------------------
// Persistent kernel: entire 512-step, 2-layer recurrence in ONE launch.
// Phase structure (independent work fused to halve barrier count):
//   phase -1 : layer0(t=0)                      | barrier
//   phase t  : layer1(t) ; layer0(t+1)          | barrier   (t = 0..510)
//   final    : layer1(511)
// ---------------------------------------------------------------------------
__global__ __launch_bounds__(256, 2)
void lstm_persistent(const float* __restrict__ x)
{
    __shared__ float As[16][68];
    __shared__ float Bs[16][68];

    const int b0 = blockIdx.y * 64;   // batch base   (gridDim.y = 4)
    const int u0 = blockIdx.x * 16;   // unit base    (gridDim.x = 32)
    unsigned target = 0;

    // layer0, t = 0
    lstm_tile(x, TT * DD, DD, K0T, g_h0[0], g_W0, g_b0, g_c0, g_h0[1],
              b0, u0, As, Bs);
    grid_barrier(target);

    for (int t = 0; t < TT - 1; t++) {
        const int p  = t & 1;
        // layer1(t): reads g_h0[p^1] (layer0 output at t) + g_h1[p]
        lstm_tile(g_h0[p ^ 1], HH, HH, K1T, g_h1[p], g_W1, g_b1, g_c1, g_h1[p ^ 1],
                  b0, u0, As, Bs);
        // layer0(t+1): reads x(t+1) + g_h0[p^1]; writes g_h0[p] (dead buffer)
        lstm_tile(x + (size_t)(t + 1) * DD, TT * DD, DD, K0T,
                  g_h0[p ^ 1], g_W0, g_b0, g_c0, g_h0[p],
                  b0, u0, As, Bs);
        grid_barrier(target);
    }

    // layer1, t = 511: p = 1, writes g_h1[0]
    lstm_tile(g_h0[0], HH, HH, K1T, g_h1[1], g_W1, g_b1, g_c1, g_h1[0],
              b0, u0, As, Bs);
}

// ---------------------------------------------------------------------------
// Final FC on last timestep: out[b] = h1_final[b,:] . fc_w + fc_b
// (layer1 at t=511 wrote g_h1[0])
// ---------------------------------------------------------------------------
__global__ void fc_kernel(const float* __restrict__ fc_w, const float* __restrict__ fc_b,
                          float* __restrict__ out)
{
    const int b = blockIdx.x;
    const float* h = g_h1[0] + (size_t)b * HH;
    float s = 0.f;
    for (int k = threadIdx.x; k < HH; k += 128) s += h[k] * fc_w[k];

    #pragma unroll
    for (int off = 16; off > 0; off >>= 1) s += __shfl_xor_sync(0xffffffffu, s, off);

    __shared__ float ws[4];
    if ((threadIdx.x & 31) == 0) ws[threadIdx.x >> 5] = s;
    __syncthreads();
    if (threadIdx.x == 0)
        out[b] = ws[0] + ws[1] + ws[2] + ws[3] + fc_b[0];
}

// ---------------------------------------------------------------------------
extern "C" void kernel_launch(void* const* d_in, const int* in_sizes, int n_in,
                              void* d_out, int out_size)
{
    const float* x      = (const float*)d_in[0];
    const float* w_ih_0 = (const float*)d_in[1];
    const float* w_hh_0 = (const float*)d_in[2];
    const float* b_ih_0 = (const float*)d_in[3];
    const float* b_hh_0 = (const float*)d_in[4];
    const float* w_ih_1 = (const float*)d_in[5];
    const float* w_hh_1 = (const float*)d_in[6];
    const float* b_ih_1 = (const float*)d_in[7];
    const float* b_hh_1 = (const float*)d_in[8];
    const float* fc_w   = (const float*)d_in[9];
    const float* fc_b   = (const float*)d_in[10];
    float* out = (float*)d_out;

    pack_kernel<<<512, 256>>>(w_ih_0, w_hh_0, b_ih_0, b_hh_0,
                              w_ih_1, w_hh_1, b_ih_1, b_hh_1);

    dim3 grid(HH / 16, BB / 64);   // 32 x 4 = 128 persistent blocks
    lstm_persistent<<<grid, 256>>>(x);

    fc_kernel<<<BB, 128>>>(fc_w, fc_b, out);
}